// round 2
// baseline (speedup 1.0000x reference)
#include <cuda_runtime.h>

#define N_NODES 10000
#define DEG 32
#define IN_DIM 256
#define OUT_DIM 256
#define N_HEADS 8
#define HEAD_DIM 32
#define N_EDGES (N_NODES * DEG)

// ---------------- scratch (static device globals; no allocation) -------------
__device__ float g_Q[N_NODES * OUT_DIM];
__device__ float g_K[N_NODES * OUT_DIM];
__device__ float g_V[N_NODES * OUT_DIM];
__device__ float g_score[N_NODES * N_HEADS * DEG];   // [node][h][d]
__device__ int   g_nbr[N_EDGES];

// ---------------- index normalization (int64 vs int32 robustness) ------------
// jax's reference declares int64, but without x64 mode jax silently emits
// int32. Detect: if the data is int64 (little-endian), every odd 32-bit word
// of the first 64 elements is a zero high-word. Random int32 indices in
// [0,10000) make that pattern essentially impossible (P ~ 1e-256).
__global__ void convert_idx_kernel(const int* __restrict__ e32) {
    __shared__ int is64;
    if (threadIdx.x == 0) {
        int z = 1;
        for (int i = 1; i < 128; i += 2)
            if (e32[i] != 0) z = 0;
        is64 = z;
    }
    __syncthreads();
    int i = blockIdx.x * blockDim.x + threadIdx.x;
    if (i < N_EDGES)
        g_nbr[i] = is64 ? e32[2 * i] : e32[i];
}

// ---------------- kernel 1: Q/K/V GEMMs (10000x256 @ 256x256, z selects) ----
__global__ __launch_bounds__(256, 2) void qkv_kernel(
    const float* __restrict__ x,
    const float* __restrict__ WQ, const float* __restrict__ WK,
    const float* __restrict__ WV)
{
    const float* W = (blockIdx.z == 0) ? WQ : (blockIdx.z == 1) ? WK : WV;
    float* out = (blockIdx.z == 0) ? g_Q : (blockIdx.z == 1) ? g_K : g_V;

    __shared__ float As[32][65];     // [k][row], padded
    __shared__ float Bs[32][256];    // [k][col]

    const int tid = threadIdx.x;
    const int tx = tid & 15, ty = tid >> 4;
    const int row0 = blockIdx.x * 64;

    float acc[4][16];
#pragma unroll
    for (int r = 0; r < 4; r++)
#pragma unroll
        for (int i = 0; i < 16; i++) acc[r][i] = 0.f;

    for (int k0 = 0; k0 < 256; k0 += 32) {
#pragma unroll
        for (int i = 0; i < 8; i++) {
            int e = i * 256 + tid;
            int r = e >> 5, k = e & 31;
            int gr = row0 + r;
            As[k][r] = (gr < N_NODES) ? x[(size_t)gr * 256 + k0 + k] : 0.f;
        }
#pragma unroll
        for (int i = 0; i < 32; i++)
            Bs[i][tid] = W[(size_t)(k0 + i) * 256 + tid];
        __syncthreads();

#pragma unroll 4
        for (int k = 0; k < 32; k++) {
            float a0 = As[k][ty * 4 + 0], a1 = As[k][ty * 4 + 1];
            float a2 = As[k][ty * 4 + 2], a3 = As[k][ty * 4 + 3];
#pragma unroll
            for (int i = 0; i < 16; i++) {
                float b = Bs[k][tx + 16 * i];
                acc[0][i] += a0 * b; acc[1][i] += a1 * b;
                acc[2][i] += a2 * b; acc[3][i] += a3 * b;
            }
        }
        __syncthreads();
    }

#pragma unroll
    for (int r = 0; r < 4; r++) {
        int gr = row0 + ty * 4 + r;
        if (gr < N_NODES) {
#pragma unroll
            for (int i = 0; i < 16; i++)
                out[(size_t)gr * 256 + tx + 16 * i] = acc[r][i];
        }
    }
}

// ---------------- kernel 2: fused E1-GEMM + E2 + score ----------------------
// Block = 64 edges x full 256 cols. Epilogue contracts the E1 tile against
// K[nbr]*Q[node] per head (never materializing E1 to HBM), adds fused
// E2 = ea@WE2 + bE2, writes g_score[node][h][d].
__global__ __launch_bounds__(256, 2) void score_kernel(
    const float* __restrict__ ea,
    const float* __restrict__ WE1,
    const float* __restrict__ WE2,
    const float* __restrict__ bE2)
{
    __shared__ float As[32][65];
    __shared__ float Bs[32][256];
    __shared__ float W2s[32][8];
    __shared__ float sc[64][8];

    const int tid = threadIdx.x;
    const int tx = tid & 15, ty = tid >> 4;
    const int row0 = blockIdx.x * 64;   // edge base; 320000 % 64 == 0

    float acc[4][16];
    float acc2[4] = {0.f, 0.f, 0.f, 0.f};
#pragma unroll
    for (int r = 0; r < 4; r++)
#pragma unroll
        for (int i = 0; i < 16; i++) acc[r][i] = 0.f;

    for (int k0 = 0; k0 < 256; k0 += 32) {
#pragma unroll
        for (int i = 0; i < 8; i++) {
            int e = i * 256 + tid;
            int r = e >> 5, k = e & 31;
            As[k][r] = ea[(size_t)(row0 + r) * 256 + k0 + k];
        }
#pragma unroll
        for (int i = 0; i < 32; i++)
            Bs[i][tid] = WE1[(size_t)(k0 + i) * 256 + tid];
        {
            int k = tid >> 3, h = tid & 7;
            W2s[k][h] = WE2[(size_t)(k0 + k) * 8 + h];
        }
        __syncthreads();

#pragma unroll 4
        for (int k = 0; k < 32; k++) {
            float a0 = As[k][ty * 4 + 0], a1 = As[k][ty * 4 + 1];
            float a2 = As[k][ty * 4 + 2], a3 = As[k][ty * 4 + 3];
            if (tx < 8) {
                float w = W2s[k][tx];
                acc2[0] += a0 * w; acc2[1] += a1 * w;
                acc2[2] += a2 * w; acc2[3] += a3 * w;
            }
#pragma unroll
            for (int i = 0; i < 16; i++) {
                float b = Bs[k][tx + 16 * i];
                acc[0][i] += a0 * b; acc[1][i] += a1 * b;
                acc[2][i] += a2 * b; acc[3][i] += a3 * b;
            }
        }
        __syncthreads();
    }

    // E2 partials: exactly one writer (tx==h) per (row, head)
    if (tx < 8) {
#pragma unroll
        for (int r = 0; r < 4; r++) sc[ty * 4 + r][tx] = acc2[r];
    }
    __syncthreads();

    // score: per-row contraction with K[nbr]*Q[node], reduce across 16 lanes
#pragma unroll
    for (int r = 0; r < 4; r++) {
        int e = row0 + ty * 4 + r;
        int node = e >> 5;
        int nb = g_nbr[e];
        const float* Kp = g_K + (size_t)nb * 256;
        const float* Qp = g_Q + (size_t)node * 256;
        float p[8] = {0.f, 0.f, 0.f, 0.f, 0.f, 0.f, 0.f, 0.f};
#pragma unroll
        for (int i = 0; i < 16; i++) {
            int col = tx + 16 * i;            // head = i>>1
            float kq = Kp[col] * Qp[col];
            p[i >> 1] += acc[r][i] * kq;
        }
#pragma unroll
        for (int off = 8; off >= 1; off >>= 1) {
#pragma unroll
            for (int h = 0; h < 8; h++)
                p[h] += __shfl_down_sync(0xffffffffu, p[h], off, 16);
        }
        if (tx == 0) {
#pragma unroll
            for (int h = 0; h < 8; h++) sc[ty * 4 + r][h] += p[h];
        }
    }
    __syncthreads();

    for (int s = tid; s < 512; s += 256) {
        int row = s >> 3, h = s & 7;
        int e = row0 + row;
        int node = e >> 5, dd = e & 31;
        g_score[(size_t)node * 256 + h * 32 + dd] = sc[row][h] + bE2[h];
    }
}

// ---------------- kernel 3: clip + softmax + V aggregation -------------------
__global__ void softmax_agg_kernel(float* __restrict__ out)
{
    const int n = blockIdx.x;
    const int t = threadIdx.x;
    __shared__ float attn[8][32];
    __shared__ int nbr[32];

    if (t < 32) nbr[t] = g_nbr[n * 32 + t];

    const int h = t >> 5, d = t & 31;   // one warp per head
    float s = g_score[(size_t)n * 256 + h * 32 + d];
    s = fminf(fmaxf(s, -8.f), 8.f);

    float m = s;
#pragma unroll
    for (int off = 16; off; off >>= 1)
        m = fmaxf(m, __shfl_xor_sync(0xffffffffu, m, off));
    float ev = __expf(s - m);
    float sum = ev;
#pragma unroll
    for (int off = 16; off; off >>= 1)
        sum += __shfl_xor_sync(0xffffffffu, sum, off);
    attn[h][d] = ev / sum;
    __syncthreads();

    const int k = d;
    float acc = 0.f;
#pragma unroll
    for (int dd = 0; dd < 32; dd++)
        acc += attn[h][dd] * g_V[(size_t)nbr[dd] * 256 + h * 32 + k];
    out[(size_t)n * 256 + h * 32 + k] = acc;
}

// ---------------- launch -----------------------------------------------------
extern "C" void kernel_launch(void* const* d_in, const int* in_sizes, int n_in,
                              void* d_out, int out_size)
{
    const float* x   = (const float*)d_in[0];
    const int*   ei  = (const int*)  d_in[1];   // int32 view; dtype auto-detected
    const float* ea  = (const float*)d_in[2];
    const float* WQ  = (const float*)d_in[3];
    const float* WK  = (const float*)d_in[4];
    const float* WV  = (const float*)d_in[5];
    const float* WE1 = (const float*)d_in[6];
    const float* WE2 = (const float*)d_in[7];
    const float* bE2 = (const float*)d_in[8];
    float* out = (float*)d_out;

    convert_idx_kernel<<<(N_EDGES + 255) / 256, 256>>>(ei);

    dim3 g1((N_NODES + 63) / 64, 1, 3);
    qkv_kernel<<<g1, 256>>>(x, WQ, WK, WV);

    score_kernel<<<N_EDGES / 64, 256>>>(ea, WE1, WE2, bE2);

    softmax_agg_kernel<<<N_NODES, 256>>>(out);
}